// round 13
// baseline (speedup 1.0000x reference)
#include <cuda_runtime.h>

// ---------------------------------------------------------------------------
// Single fused kernel, SINGLE barrier. out[p] = prod_l (1-V[l,p]) * poly(p).
// CTA = 676-px chunk (grid = 148 = one wave), BLOCK = 896 (28 warps).
//
// R13 structure:
//  stream phase (all warps): eta-LUT line constants; lines inside chunk+-20A
//    stashed to smem slots (slot = l & 255, sorted-contiguous, no alias);
//    lines outside accumulate linearized lorentz at 4 chunk nodes (batched
//    rcp); per-warp partials to smem.  ONE __syncthreads().
//  back half (pixel warps 0..21, fully warp-local; warps 22..27 exit):
//    - far-node reduction per warp (lane-parallel shfl tree over partials)
//    - ballot classification of the +-4A exact window within [alo,ahi)
//    - warp-field: ALL other stashed lines (up to 20A away) via lorentz at
//      3 warp nodes, quadratic interp (err ~1.5e-7 at d=4A, ~d^-5 falloff)
//    - warp-near: exact voigt, paired rcp
//    - epilogue: cubic far interp + quadratic warp interp + poly, store.
// No CTA-mid level, no sMid, no second barrier -> slow-warp tail no longer
// serializes the whole CTA.
// ---------------------------------------------------------------------------

#define BLOCK     896
#define NWARPS    28
#define CHUNK     676
#define AWIN      20.0f
#define WNWIN     4.0f
#define STASH     256
#define SMASK     255
#define LOG2E     1.4426950408889634f
#define FULLM     0xFFFFFFFFu

__device__ __forceinline__ float frcp(float x) {
    float r; asm("rcp.approx.ftz.f32 %0, %1;" : "=f"(r) : "f"(x)); return r;
}
__device__ __forceinline__ float fex2(float x) {
    float r; asm("ex2.approx.ftz.f32 %0, %1;" : "=f"(r) : "f"(x)); return r;
}
__device__ __forceinline__ float flg2(float x) {
    float r; asm("lg2.approx.ftz.f32 %0, %1;" : "=f"(r) : "f"(x)); return r;
}

__global__ void __launch_bounds__(BLOCK)
fused_kernel(const float* __restrict__ wl, int npix, int L,
             const float* __restrict__ lam,
             const float* __restrict__ amps,
             const float* __restrict__ sw,
             const float* __restrict__ gw,
             const float* __restrict__ pa,
             const float* __restrict__ pb,
             const float* __restrict__ pc,
             float* __restrict__ out) {
    __shared__ float  sLUT[129];
    __shared__ float4 sA[STASH];             // slot l&255: {lam, g^2, c_lor, m}
    __shared__ float  sB[STASH];             // c_gauss
    __shared__ float  sWredF[4 * NWARPS];    // far partials per warp
    __shared__ int    sIdx[2];               // {min stash l, max stash l}

    const int tid  = threadIdx.x;
    const int w    = tid >> 5, lane = tid & 31;
    const int p0   = blockIdx.x * CHUNK;
    const int cnt  = min(CHUNK, npix - p0);
    const int p    = p0 + tid;

    // ---- early loads (issue now, consume late) ----
    const float wlp = wl[min(p, npix - 1)];
    const float cpa = pa[0], cpb = pb[0], cpc = pc[0];
    const float wlLo = wl[p0];
    const float wlHi = wl[p0 + cnt - 1];

    const int nq = L >> 2;
    float4 l4, a4, s4, g4;
    const bool act0 = tid < nq;
    if (act0) {
        l4 = ((const float4*)lam)[tid];
        a4 = ((const float4*)amps)[tid];
        s4 = ((const float4*)sw)[tid];
        g4 = ((const float4*)gw)[tid];
    }

    const float span = wlHi - wlLo;
    const float b0 = wlLo - AWIN, b3 = wlHi + AWIN;
    const float n1w = fmaf(span, 1.0f / 3.0f, wlLo);
    const float n2w = fmaf(span, 2.0f / 3.0f, wlLo);

    if (tid == 0) { sIdx[0] = 0x7FFFFFFF; sIdx[1] = -1; }
    if (tid < 129) {
        float u = fmaf((float)tid, 0.0375f, -2.4f);
        float r = 0.8492866f * fex2(u * LOG2E);           // fl/fg
        float P = 1.0f + r * (2.69269f + r * (2.42843f
                 + r * (4.47163f + r * (0.07842f + r))));
        float fr = r * fex2(-0.2f * flg2(P));             // fl/fwhm
        sLUT[tid] = fr * (1.36603f + fr * (-0.47719f + fr * 0.11116f));
    }
    __syncthreads();   // LUT + sIdx init visible (barrier #1 of 2 total)

    // ---- stream all lines: LUT constants + far sums + slot stash ----
    float S0 = 0.f, S1 = 0.f, S2 = 0.f, S3 = 0.f;

    auto body = [&](int l, float lc, float av, float swv, float gwv) {
        float fi = fmaf(gwv - swv, 26.6666667f, 64.0f);
        fi = fminf(fmaxf(fi, 0.0f), 127.99f);
        int   ii  = (int)fi;
        float fr8 = fi - (float)ii;
        float el  = sLUT[ii], eh = sLUT[ii + 1];
        float eta = fmaf(fr8, eh - el, el);

        float gamma = fex2(gwv * LOG2E);
        float ag    = fex2((av + gwv) * LOG2E);           // amp*gamma
        float g2 = gamma * gamma;
        float cl = ag * eta * 0.3183098862f;

        if (lc >= b0 && lc < b3) {
            float m  = -0.72134752f * fex2(-2.0f * swv * LOG2E);
            float cg = (1.0f - eta) * 0.39894228f * fex2((av - swv) * LOG2E);
            int slot = l & SMASK;
            sA[slot] = make_float4(lc, g2, cl, m);
            sB[slot] = cg;
            atomicMin(&sIdx[0], l);
            atomicMax(&sIdx[1], l);
        } else {
            float d0 = wlLo - lc, d1 = n1w - lc, d2 = n2w - lc, d3 = wlHi - lc;
            float e0 = fmaf(d0, d0, g2), e1 = fmaf(d1, d1, g2);
            float e2 = fmaf(d2, d2, g2), e3 = fmaf(d3, d3, g2);
            float p01 = e0 * e1, p23 = e2 * e3;
            float r   = frcp(p01 * p23);
            float r01 = r * p23, r23 = r * p01;
            S0 = fmaf(cl * e1, r01, S0);
            S1 = fmaf(cl * e0, r01, S1);
            S2 = fmaf(cl * e3, r23, S2);
            S3 = fmaf(cl * e2, r23, S3);
        }
    };

    if (act0) {
        int lb = tid * 4;
        body(lb + 0, l4.x, a4.x, s4.x, g4.x);
        body(lb + 1, l4.y, a4.y, s4.y, g4.y);
        body(lb + 2, l4.z, a4.z, s4.z, g4.z);
        body(lb + 3, l4.w, a4.w, s4.w, g4.w);
    }
    for (int t = tid + BLOCK; t < nq; t += BLOCK) {
        float4 lv = ((const float4*)lam)[t];
        float4 av = ((const float4*)amps)[t];
        float4 sv = ((const float4*)sw)[t];
        float4 gv = ((const float4*)gw)[t];
        int lb = t * 4;
        body(lb + 0, lv.x, av.x, sv.x, gv.x);
        body(lb + 1, lv.y, av.y, sv.y, gv.y);
        body(lb + 2, lv.z, av.z, sv.z, gv.z);
        body(lb + 3, lv.w, av.w, sv.w, gv.w);
    }
    for (int l = (nq << 2) + tid; l < L; l += BLOCK)
        body(l, lam[l], amps[l], sw[l], gw[l]);

    #pragma unroll
    for (int o = 16; o; o >>= 1) {
        S0 += __shfl_xor_sync(FULLM, S0, o);
        S1 += __shfl_xor_sync(FULLM, S1, o);
        S2 += __shfl_xor_sync(FULLM, S2, o);
        S3 += __shfl_xor_sync(FULLM, S3, o);
    }
    if (lane == 0) {
        sWredF[w]              = S0;
        sWredF[NWARPS + w]     = S1;
        sWredF[2 * NWARPS + w] = S2;
        sWredF[3 * NWARPS + w] = S3;
    }
    __syncthreads();   // stash + partials visible — LAST barrier

    if (w >= 22) return;   // collective warps done; free the issue slots

    // ================== warp-local back half ==================
    int alo = sIdx[0], ahi = sIdx[1] + 1;
    if (ahi <= alo) { alo = 0; ahi = 0; }
    ahi = min(ahi, alo + STASH);

    // far-node sums: lane-parallel reduction of per-warp partials
    float Sn0, Sn1, Sn2, Sn3;
    {
        float v0 = (lane < NWARPS) ? sWredF[lane]              : 0.f;
        float v1 = (lane < NWARPS) ? sWredF[NWARPS + lane]     : 0.f;
        float v2 = (lane < NWARPS) ? sWredF[2 * NWARPS + lane] : 0.f;
        float v3 = (lane < NWARPS) ? sWredF[3 * NWARPS + lane] : 0.f;
        #pragma unroll
        for (int o = 16; o; o >>= 1) {
            v0 += __shfl_xor_sync(FULLM, v0, o);
            v1 += __shfl_xor_sync(FULLM, v1, o);
            v2 += __shfl_xor_sync(FULLM, v2, o);
            v3 += __shfl_xor_sync(FULLM, v3, o);
        }
        Sn0 = v0; Sn1 = v1; Sn2 = v2; Sn3 = v3;
    }

    // classification: exact window = warp span +- 4A, ballot over [alo,ahi)
    const float x0n = __shfl_sync(FULLM, wlp, 0);
    const float x2n = __shfl_sync(FULLM, wlp, 31);
    const float wLo = x0n - WNWIN, wHi = x2n + WNWIN;
    int glo = ahi, ghi = alo;
    for (int base = alo; base < ahi; base += 32) {
        int idx = base + lane;
        bool in = (idx < ahi) && (sA[idx & SMASK].x >= wLo)
                              && (sA[idx & SMASK].x <= wHi);
        unsigned m = __ballot_sync(FULLM, in);
        if (m) {
            glo = min(glo, base + (__ffs(m) - 1));
            ghi = max(ghi, base + (31 - __clz(m)) + 1);
        }
    }
    if (ghi < glo) { glo = alo; ghi = alo; }

    // warp-field: all other stashed lines, lorentz at 3 warp nodes
    const float x1n = 0.5f * (x0n + x2n);
    float M0 = 0.f, M1 = 0.f, M2 = 0.f;
    for (int j = alo + lane; j < ahi; j += 32) {
        if (j >= glo && j < ghi) continue;       // exact-handled
        float4 a = sA[j & SMASK];
        float d0 = x0n - a.x, d1 = x1n - a.x, d2 = x2n - a.x;
        float e0 = fmaf(d0, d0, a.y);
        float e1 = fmaf(d1, d1, a.y);
        float e2 = fmaf(d2, d2, a.y);
        float p01 = e0 * e1;
        float r   = frcp(p01 * e2);
        float r01 = r * e2;
        M0 = fmaf(a.z * e1, r01, M0);
        M1 = fmaf(a.z * e0, r01, M1);
        M2 = fmaf(a.z, r * p01, M2);
    }
    #pragma unroll
    for (int o = 16; o; o >>= 1) {
        M0 += __shfl_xor_sync(FULLM, M0, o);
        M1 += __shfl_xor_sync(FULLM, M1, o);
        M2 += __shfl_xor_sync(FULLM, M2, o);
    }

    // warp-near: exact voigt product, paired rcp
    float prodA = 1.0f, prodB = 1.0f;
    int j = glo;
    for (; j + 1 < ghi; j += 2) {
        float4 a0 = sA[j & SMASK];       float cg0 = sB[j & SMASK];
        float4 a1 = sA[(j + 1) & SMASK]; float cg1 = sB[(j + 1) & SMASK];
        float dd0 = wlp - a0.x, dd1 = wlp - a1.x;
        float q0 = dd0 * dd0,   q1 = dd1 * dd1;
        float e0 = q0 + a0.y,   e1 = q1 + a1.y;
        float r  = frcp(e0 * e1);
        float v0 = fmaf(cg0, fex2(q0 * a0.w), (a0.z * e1) * r);
        float v1 = fmaf(cg1, fex2(q1 * a1.w), (a1.z * e0) * r);
        prodA = fmaf(-v0, prodA, prodA);
        prodB = fmaf(-v1, prodB, prodB);
    }
    if (j < ghi) {
        float4 a = sA[j & SMASK]; float cg = sB[j & SMASK];
        float dd = wlp - a.x;
        float q  = dd * dd;
        float v  = fmaf(cg, fex2(q * a.w), a.z * frcp(q + a.y));
        prodA = fmaf(-v, prodA, prodA);
    }
    float prod = prodA * prodB;

    // ---- epilogue (warp-local, no barrier needed) ----
    if (tid < cnt && p < npix) {
        const float ic = frcp((float)(cnt - 1));

        // CTA-far: cubic Lagrange on chunk nodes {0,1,2,3}, s in [0,3]
        float s = (float)tid * (3.0f * ic);
        float sm1 = s - 1.0f, sm2 = s - 2.0f, sm3 = s - 3.0f;
        float Sfar = (sm1 * sm2 * sm3) * (-1.0f / 6.0f) * Sn0
                   + (s   * sm2 * sm3) * ( 0.5f       ) * Sn1
                   + (s   * sm1 * sm3) * (-0.5f       ) * Sn2
                   + (s   * sm1 * sm2) * ( 1.0f / 6.0f) * Sn3;

        // warp-field: quadratic on warp nodes {x0n, x1n, x2n}, u in [0,2]
        float hw = 0.5f * (x2n - x0n);
        float u  = (wlp - x0n) * frcp(hw);
        float um1 = u - 1.0f, um2 = u - 2.0f;
        float Swm = (um1 * um2 * 0.5f) * M0
                  + (u * (2.0f - u)  ) * M1
                  + (u * um1 * 0.5f  ) * M2;

        float xw   = (wlp - 10500.0f) * (1.0f / 2500.0f);
        float polw = cpa + (cpb + cpc * xw) * xw;
        out[p] = prod * fex2(-(Sfar + Swm) * (float)LOG2E) * polw;
    }
}

extern "C" void kernel_launch(void* const* d_in, const int* in_sizes, int n_in,
                              void* d_out, int out_size) {
    const float* wl   = (const float*)d_in[0];
    const float* lam  = (const float*)d_in[1];
    const float* amps = (const float*)d_in[2];
    const float* sw   = (const float*)d_in[3];
    const float* gw   = (const float*)d_in[4];
    const float* pa   = (const float*)d_in[5];
    const float* pb   = (const float*)d_in[6];
    const float* pc   = (const float*)d_in[7];
    float* out = (float*)d_out;

    int npix = in_sizes[0];
    int L    = in_sizes[1];

    int nchunks = (npix + CHUNK - 1) / CHUNK;
    fused_kernel<<<nchunks, BLOCK>>>(wl, npix, L, lam, amps, sw, gw,
                                     pa, pb, pc, out);
}

// round 14
// speedup vs baseline: 1.0089x; 1.0089x over previous
#include <cuda_runtime.h>

// ---------------------------------------------------------------------------
// Single fused kernel. out[p] = prod_l (1 - V[l,p]) * poly(p), V pseudo-Voigt.
// CTA = 676-px chunk (grid = 148 = one wave), BLOCK = 768 (24 warps).
//
// R14:
//  - far field (> 20 A): linearized lorentz at TWO chunk-end nodes, LINEAR
//    interp (summed curvature ~1.2e-6/A^2 -> err <= ~7e-6). Halves the
//    dominant per-line stream math vs 4-node cubic.
//  - exact window tightened to +-2.7 A of the warp span (gauss dead beyond
//    2.52 A worst-case; warp-field quadratic err ~1.3e-6 at 2.7 A).
//  - BLOCK 768: stream uses 750 threads (L/4 float4 strips), pixels use 676.
// Structure else as R13: eta-LUT, slot stash (l & 255), one main barrier,
// warp-local back half (far reduction, ballot classify, warp-field quad,
// warp-near exact with paired rcp), warps 22..23 exit early.
// ---------------------------------------------------------------------------

#define BLOCK     768
#define NWARPS    24
#define CHUNK     676
#define AWIN      20.0f
#define WNWIN     2.7f
#define STASH     256
#define SMASK     255
#define LOG2E     1.4426950408889634f
#define FULLM     0xFFFFFFFFu

__device__ __forceinline__ float frcp(float x) {
    float r; asm("rcp.approx.ftz.f32 %0, %1;" : "=f"(r) : "f"(x)); return r;
}
__device__ __forceinline__ float fex2(float x) {
    float r; asm("ex2.approx.ftz.f32 %0, %1;" : "=f"(r) : "f"(x)); return r;
}
__device__ __forceinline__ float flg2(float x) {
    float r; asm("lg2.approx.ftz.f32 %0, %1;" : "=f"(r) : "f"(x)); return r;
}

__global__ void __launch_bounds__(BLOCK)
fused_kernel(const float* __restrict__ wl, int npix, int L,
             const float* __restrict__ lam,
             const float* __restrict__ amps,
             const float* __restrict__ sw,
             const float* __restrict__ gw,
             const float* __restrict__ pa,
             const float* __restrict__ pb,
             const float* __restrict__ pc,
             float* __restrict__ out) {
    __shared__ float  sLUT[129];
    __shared__ float4 sA[STASH];             // slot l&255: {lam, g^2, c_lor, m}
    __shared__ float  sB[STASH];             // c_gauss
    __shared__ float  sWredF[2 * NWARPS];    // far partials per warp (2 nodes)
    __shared__ int    sIdx[2];               // {min stash l, max stash l}

    const int tid  = threadIdx.x;
    const int w    = tid >> 5, lane = tid & 31;
    const int p0   = blockIdx.x * CHUNK;
    const int cnt  = min(CHUNK, npix - p0);
    const int p    = p0 + tid;

    // ---- early loads (issue now, consume late) ----
    const float wlp = wl[min(p, npix - 1)];
    const float cpa = pa[0], cpb = pb[0], cpc = pc[0];
    const float wlLo = wl[p0];
    const float wlHi = wl[p0 + cnt - 1];

    const int nq = L >> 2;
    float4 l4, a4, s4, g4;
    const bool act0 = tid < nq;
    if (act0) {
        l4 = ((const float4*)lam)[tid];
        a4 = ((const float4*)amps)[tid];
        s4 = ((const float4*)sw)[tid];
        g4 = ((const float4*)gw)[tid];
    }

    const float b0 = wlLo - AWIN, b3 = wlHi + AWIN;

    if (tid == 0) { sIdx[0] = 0x7FFFFFFF; sIdx[1] = -1; }
    if (tid < 129) {
        float u = fmaf((float)tid, 0.0375f, -2.4f);
        float r = 0.8492866f * fex2(u * LOG2E);           // fl/fg
        float P = 1.0f + r * (2.69269f + r * (2.42843f
                 + r * (4.47163f + r * (0.07842f + r))));
        float fr = r * fex2(-0.2f * flg2(P));             // fl/fwhm
        sLUT[tid] = fr * (1.36603f + fr * (-0.47719f + fr * 0.11116f));
    }
    __syncthreads();   // LUT + sIdx init visible

    // ---- stream all lines: LUT constants + 2-node far sums + slot stash ----
    float S0 = 0.f, S1 = 0.f;

    auto body = [&](int l, float lc, float av, float swv, float gwv) {
        float fi = fmaf(gwv - swv, 26.6666667f, 64.0f);
        fi = fminf(fmaxf(fi, 0.0f), 127.99f);
        int   ii  = (int)fi;
        float fr8 = fi - (float)ii;
        float el  = sLUT[ii], eh = sLUT[ii + 1];
        float eta = fmaf(fr8, eh - el, el);

        float gamma = fex2(gwv * LOG2E);
        float ag    = fex2((av + gwv) * LOG2E);           // amp*gamma
        float g2 = gamma * gamma;
        float cl = ag * eta * 0.3183098862f;

        if (lc >= b0 && lc < b3) {
            float m  = -0.72134752f * fex2(-2.0f * swv * LOG2E);
            float cg = (1.0f - eta) * 0.39894228f * fex2((av - swv) * LOG2E);
            int slot = l & SMASK;
            sA[slot] = make_float4(lc, g2, cl, m);
            sB[slot] = cg;
            atomicMin(&sIdx[0], l);
            atomicMax(&sIdx[1], l);
        } else {
            float d0 = wlLo - lc, d1 = wlHi - lc;
            float e0 = fmaf(d0, d0, g2), e1 = fmaf(d1, d1, g2);
            float r  = frcp(e0 * e1);
            float cr = cl * r;
            S0 = fmaf(cr, e1, S0);
            S1 = fmaf(cr, e0, S1);
        }
    };

    if (act0) {
        int lb = tid * 4;
        body(lb + 0, l4.x, a4.x, s4.x, g4.x);
        body(lb + 1, l4.y, a4.y, s4.y, g4.y);
        body(lb + 2, l4.z, a4.z, s4.z, g4.z);
        body(lb + 3, l4.w, a4.w, s4.w, g4.w);
    }
    for (int t = tid + BLOCK; t < nq; t += BLOCK) {
        float4 lv = ((const float4*)lam)[t];
        float4 av = ((const float4*)amps)[t];
        float4 sv = ((const float4*)sw)[t];
        float4 gv = ((const float4*)gw)[t];
        int lb = t * 4;
        body(lb + 0, lv.x, av.x, sv.x, gv.x);
        body(lb + 1, lv.y, av.y, sv.y, gv.y);
        body(lb + 2, lv.z, av.z, sv.z, gv.z);
        body(lb + 3, lv.w, av.w, sv.w, gv.w);
    }
    for (int l = (nq << 2) + tid; l < L; l += BLOCK)
        body(l, lam[l], amps[l], sw[l], gw[l]);

    #pragma unroll
    for (int o = 16; o; o >>= 1) {
        S0 += __shfl_xor_sync(FULLM, S0, o);
        S1 += __shfl_xor_sync(FULLM, S1, o);
    }
    if (lane == 0) {
        sWredF[w]          = S0;
        sWredF[NWARPS + w] = S1;
    }
    __syncthreads();   // stash + partials visible — LAST barrier

    if (w >= 22) return;   // non-pixel warps done

    // ================== warp-local back half ==================
    int alo = sIdx[0], ahi = sIdx[1] + 1;
    if (ahi <= alo) { alo = 0; ahi = 0; }
    ahi = min(ahi, alo + STASH);

    // far-node sums: lane-parallel reduction of per-warp partials
    float Sn0, Sn1;
    {
        float v0 = (lane < NWARPS) ? sWredF[lane]          : 0.f;
        float v1 = (lane < NWARPS) ? sWredF[NWARPS + lane] : 0.f;
        #pragma unroll
        for (int o = 16; o; o >>= 1) {
            v0 += __shfl_xor_sync(FULLM, v0, o);
            v1 += __shfl_xor_sync(FULLM, v1, o);
        }
        Sn0 = v0; Sn1 = v1;
    }

    // classification: exact window = warp span +- 2.7A, ballot over [alo,ahi)
    const float x0n = __shfl_sync(FULLM, wlp, 0);
    const float x2n = __shfl_sync(FULLM, wlp, 31);
    const float wLo = x0n - WNWIN, wHi = x2n + WNWIN;
    int glo = ahi, ghi = alo;
    for (int base = alo; base < ahi; base += 32) {
        int idx = base + lane;
        bool in = (idx < ahi) && (sA[idx & SMASK].x >= wLo)
                              && (sA[idx & SMASK].x <= wHi);
        unsigned m = __ballot_sync(FULLM, in);
        if (m) {
            glo = min(glo, base + (__ffs(m) - 1));
            ghi = max(ghi, base + (31 - __clz(m)) + 1);
        }
    }
    if (ghi < glo) { glo = alo; ghi = alo; }

    // warp-field: all other stashed lines, lorentz at 3 warp nodes
    const float x1n = 0.5f * (x0n + x2n);
    float M0 = 0.f, M1 = 0.f, M2 = 0.f;
    for (int j = alo + lane; j < ahi; j += 32) {
        if (j >= glo && j < ghi) continue;       // exact-handled
        float4 a = sA[j & SMASK];
        float d0 = x0n - a.x, d1 = x1n - a.x, d2 = x2n - a.x;
        float e0 = fmaf(d0, d0, a.y);
        float e1 = fmaf(d1, d1, a.y);
        float e2 = fmaf(d2, d2, a.y);
        float p01 = e0 * e1;
        float r   = frcp(p01 * e2);
        float r01 = r * e2;
        M0 = fmaf(a.z * e1, r01, M0);
        M1 = fmaf(a.z * e0, r01, M1);
        M2 = fmaf(a.z, r * p01, M2);
    }
    #pragma unroll
    for (int o = 16; o; o >>= 1) {
        M0 += __shfl_xor_sync(FULLM, M0, o);
        M1 += __shfl_xor_sync(FULLM, M1, o);
        M2 += __shfl_xor_sync(FULLM, M2, o);
    }

    // warp-near: exact voigt product, paired rcp
    float prodA = 1.0f, prodB = 1.0f;
    int j = glo;
    for (; j + 1 < ghi; j += 2) {
        float4 a0 = sA[j & SMASK];       float cg0 = sB[j & SMASK];
        float4 a1 = sA[(j + 1) & SMASK]; float cg1 = sB[(j + 1) & SMASK];
        float dd0 = wlp - a0.x, dd1 = wlp - a1.x;
        float q0 = dd0 * dd0,   q1 = dd1 * dd1;
        float e0 = q0 + a0.y,   e1 = q1 + a1.y;
        float r  = frcp(e0 * e1);
        float v0 = fmaf(cg0, fex2(q0 * a0.w), (a0.z * e1) * r);
        float v1 = fmaf(cg1, fex2(q1 * a1.w), (a1.z * e0) * r);
        prodA = fmaf(-v0, prodA, prodA);
        prodB = fmaf(-v1, prodB, prodB);
    }
    if (j < ghi) {
        float4 a = sA[j & SMASK]; float cg = sB[j & SMASK];
        float dd = wlp - a.x;
        float q  = dd * dd;
        float v  = fmaf(cg, fex2(q * a.w), a.z * frcp(q + a.y));
        prodA = fmaf(-v, prodA, prodA);
    }
    float prod = prodA * prodB;

    // ---- epilogue (warp-local) ----
    if (tid < cnt && p < npix) {
        // far: linear between chunk-end nodes
        float s = (float)tid * frcp((float)(cnt - 1));
        float Sfar = fmaf(s, Sn1 - Sn0, Sn0);

        // warp-field: quadratic on warp nodes {x0n, x1n, x2n}, u in [0,2]
        float hw = 0.5f * (x2n - x0n);
        float u  = (wlp - x0n) * frcp(hw);
        float um1 = u - 1.0f, um2 = u - 2.0f;
        float Swm = (um1 * um2 * 0.5f) * M0
                  + (u * (2.0f - u)  ) * M1
                  + (u * um1 * 0.5f  ) * M2;

        float xw   = (wlp - 10500.0f) * (1.0f / 2500.0f);
        float polw = cpa + (cpb + cpc * xw) * xw;
        out[p] = prod * fex2(-(Sfar + Swm) * (float)LOG2E) * polw;
    }
}

extern "C" void kernel_launch(void* const* d_in, const int* in_sizes, int n_in,
                              void* d_out, int out_size) {
    const float* wl   = (const float*)d_in[0];
    const float* lam  = (const float*)d_in[1];
    const float* amps = (const float*)d_in[2];
    const float* sw   = (const float*)d_in[3];
    const float* gw   = (const float*)d_in[4];
    const float* pa   = (const float*)d_in[5];
    const float* pb   = (const float*)d_in[6];
    const float* pc   = (const float*)d_in[7];
    float* out = (float*)d_out;

    int npix = in_sizes[0];
    int L    = in_sizes[1];

    int nchunks = (npix + CHUNK - 1) / CHUNK;
    fused_kernel<<<nchunks, BLOCK>>>(wl, npix, L, lam, amps, sw, gw,
                                     pa, pb, pc, out);
}